// round 7
// baseline (speedup 1.0000x reference)
#include <cuda_runtime.h>
#include <cuda_bf16.h>
#include <math.h>
#include <stdint.h>

#define Bc   4
#define Nc   8192
#define Gc   512
#define K1   1536
#define K2   512
#define Mtot (Bc * Nc)   // 32768
#define Mg   (Bc * Gc)   // 2048

// ---------------- scratch ----------------------------------------------------
__device__ unsigned short g_Fh[(size_t)Mg * K1];     // fused features hi (bf16)
__device__ unsigned short g_Fl[(size_t)Mg * K1];     // fused features lo
__device__ float          g_P [(size_t)Mg * 512];    // F @ W1^T (raw fp32)
__device__ unsigned short g_w1h[512 * K1], g_w1l[512 * K1];
__device__ unsigned short g_w2h[512 * K2], g_w2l[512 * K2];
__device__ int   g_idx[Mtot * 3];
__device__ float g_wts[Mtot * 3];
__device__ float g_s1[512], g_t1[512], g_s2[512], g_t2[512];

// ---------------- helpers ----------------------------------------------------
__device__ __forceinline__ uint32_t smem_u32(const void* p) {
    uint32_t a;
    asm("{ .reg .u64 t; cvta.to.shared.u64 t, %1; cvt.u32.u64 %0, t; }" : "=r"(a) : "l"(p));
    return a;
}
__device__ __forceinline__ void cp_async16(uint32_t dst, const void* src) {
    asm volatile("cp.async.cg.shared.global [%0], [%1], 16;" :: "r"(dst), "l"(src));
}
#define CP_COMMIT() asm volatile("cp.async.commit_group;" ::: "memory")
#define CP_WAIT(n)  asm volatile("cp.async.wait_group %0;" :: "n"(n) : "memory")

__device__ __forceinline__ void ldm_x4(uint32_t* r, uint32_t a) {
    asm volatile("ldmatrix.sync.aligned.m8n8.x4.shared.b16 {%0,%1,%2,%3}, [%4];"
                 : "=r"(r[0]), "=r"(r[1]), "=r"(r[2]), "=r"(r[3]) : "r"(a));
}
__device__ __forceinline__ void mma_bf16(float* c, const uint32_t* a, const uint32_t* b) {
    asm volatile("mma.sync.aligned.m16n8k16.row.col.f32.bf16.bf16.f32 "
                 "{%0,%1,%2,%3}, {%4,%5,%6,%7}, {%8,%9}, {%0,%1,%2,%3};"
                 : "+f"(c[0]), "+f"(c[1]), "+f"(c[2]), "+f"(c[3])
                 : "r"(a[0]), "r"(a[1]), "r"(a[2]), "r"(a[3]), "r"(b[0]), "r"(b[1]));
}
__device__ __forceinline__ uint32_t swz(uint32_t o) { return o ^ ((o >> 3) & 0x70); }
__device__ __forceinline__ unsigned short bfhi(float v) {
    __nv_bfloat16 h = __float2bfloat16(v);
    return *(unsigned short*)&h;
}
__device__ __forceinline__ unsigned short bflo(float v, unsigned short hb) {
    __nv_bfloat16 h; *(unsigned short*)&h = hb;
    __nv_bfloat16 l = __float2bfloat16(v - __bfloat162float(h));
    return *(unsigned short*)&l;
}

// ---------------------------------------------------------------------------
__global__ void prep_kernel(const float* __restrict__ b1, const float* __restrict__ g1,
                            const float* __restrict__ be1, const float* __restrict__ m1,
                            const float* __restrict__ v1,
                            const float* __restrict__ b2, const float* __restrict__ g2,
                            const float* __restrict__ be2, const float* __restrict__ m2,
                            const float* __restrict__ v2) {
    int i = threadIdx.x;
    if (i < 512) {
        float s = g1[i] * rsqrtf(v1[i] + 1e-5f);
        g_s1[i] = s;
        g_t1[i] = (b1[i] - m1[i]) * s + be1[i];
        float s2 = g2[i] * rsqrtf(v2[i] + 1e-5f);
        g_s2[i] = s2;
        g_t2[i] = (b2[i] - m2[i]) * s2 + be2[i];
    }
}

__global__ void convw_kernel(const float* __restrict__ w1, const float* __restrict__ w2) {
    int i = blockIdx.x * 256 + threadIdx.x;
    if (i < 512 * K1) {
        float v = w1[i];
        unsigned short h = bfhi(v);
        g_w1h[i] = h;
        g_w1l[i] = bflo(v, h);
    }
    if (i < 512 * K2) {
        float v = w2[i];
        unsigned short h = bfhi(v);
        g_w2h[i] = h;
        g_w2l[i] = bflo(v, h);
    }
}

// fused features F -> bf16 hi/lo
__global__ void convF_kernel(const float4* __restrict__ H4,
                             const float4* __restrict__ H8,
                             const float4* __restrict__ H12) {
    int gid = blockIdx.x * 256 + threadIdx.x;   // < Mg * 384
    if (gid >= Mg * 384) return;
    int row = gid / 384;
    int c4  = gid - row * 384;
    int seg = c4 >> 7;
    int off = c4 & 127;
    const float4* H = (seg == 0) ? H4 : ((seg == 1) ? H8 : H12);
    float4 v = H[(size_t)row * 128 + off];
    float o[4] = {v.x, v.y, v.z, v.w};
    union { unsigned short u[4]; uint2 q; } Hq, Lq;
#pragma unroll
    for (int j = 0; j < 4; j++) {
        Hq.u[j] = bfhi(o[j]);
        Lq.u[j] = bflo(o[j], Hq.u[j]);
    }
    *reinterpret_cast<uint2*>(g_Fh + (size_t)gid * 4) = Hq.q;
    *reinterpret_cast<uint2*>(g_Fl + (size_t)gid * 4) = Lq.q;
}

// ---------------------------------------------------------------------------
// 3-NN, 4 threads per point (chunks of 128 centers each), bit-exact insertion,
// order-preserving shfl merge (chunk order == index order, strict-< inserts).
// ---------------------------------------------------------------------------
__global__ void knn_kernel(const float* __restrict__ xyz,
                           const float* __restrict__ centers) {
    __shared__ float4 sc[Gc];
    const int tid = threadIdx.x;
    const int p = blockIdx.x * 64 + (tid >> 2);   // 64 points per block
    const int q = tid & 3;                        // chunk id
    const int b = p >> 13;
    for (int g = tid; g < Gc; g += 256) {
        float cx = centers[(b * Gc + g) * 3 + 0];
        float cy = centers[(b * Gc + g) * 3 + 1];
        float cz = centers[(b * Gc + g) * 3 + 2];
        float cc = __fadd_rn(__fadd_rn(__fmul_rn(cx, cx), __fmul_rn(cy, cy)),
                             __fmul_rn(cz, cz));
        sc[g] = make_float4(cx, cy, cz, cc);
    }
    __syncthreads();

    float x = xyz[p * 3 + 0], y = xyz[p * 3 + 1], z = xyz[p * 3 + 2];
    float xx = __fadd_rn(__fadd_rn(__fmul_rn(x, x), __fmul_rn(y, y)),
                         __fmul_rn(z, z));
    float dd[3] = {INFINITY, INFINITY, INFINITY};
    int   ii[3] = {0, 0, 0};
    const int gbeg = q * 128;
#pragma unroll 4
    for (int g = gbeg; g < gbeg + 128; g++) {
        float4 c = sc[g];
        float dot = __fmaf_rn(z, c.z, __fmaf_rn(y, c.y, __fmul_rn(x, c.x)));
        float d   = __fsub_rn(__fadd_rn(xx, c.w), __fmul_rn(2.0f, dot));
        if (d < dd[0])      { dd[2]=dd[1]; ii[2]=ii[1]; dd[1]=dd[0]; ii[1]=ii[0]; dd[0]=d; ii[0]=g; }
        else if (d < dd[1]) { dd[2]=dd[1]; ii[2]=ii[1]; dd[1]=d; ii[1]=g; }
        else if (d < dd[2]) { dd[2]=d; ii[2]=g; }
    }
    // merge chunks 1..3 into chunk-0 lane's triplet (all lanes compute; q==0 valid)
    float md[3] = {dd[0], dd[1], dd[2]};
    int   mi[3] = {ii[0], ii[1], ii[2]};
#pragma unroll
    for (int src = 1; src < 4; src++) {
#pragma unroll
        for (int j = 0; j < 3; j++) {
            float dc = __shfl_sync(0xFFFFFFFF, dd[j], src, 4);
            int   ic = __shfl_sync(0xFFFFFFFF, ii[j], src, 4);
            if (dc < md[0])      { md[2]=md[1]; mi[2]=mi[1]; md[1]=md[0]; mi[1]=mi[0]; md[0]=dc; mi[0]=ic; }
            else if (dc < md[1]) { md[2]=md[1]; mi[2]=mi[1]; md[1]=dc; mi[1]=ic; }
            else if (dc < md[2]) { md[2]=dc; mi[2]=ic; }
        }
    }
    if (q == 0) {
        float r0 = __fdiv_rn(1.0f, __fadd_rn(md[0], 1e-8f));
        float r1 = __fdiv_rn(1.0f, __fadd_rn(md[1], 1e-8f));
        float r2 = __fdiv_rn(1.0f, __fadd_rn(md[2], 1e-8f));
        float rs = __fadd_rn(__fadd_rn(r0, r1), r2);
        g_idx[p * 3 + 0] = mi[0]; g_idx[p * 3 + 1] = mi[1]; g_idx[p * 3 + 2] = mi[2];
        g_wts[p * 3 + 0] = __fdiv_rn(r0, rs);
        g_wts[p * 3 + 1] = __fdiv_rn(r1, rs);
        g_wts[p * 3 + 2] = __fdiv_rn(r2, rs);
    }
}

// ---------------------------------------------------------------------------
// GEMM1: P[2048,512] = F @ W1^T (3-term bf16 split, raw fp32 out). Validated R6.
// ---------------------------------------------------------------------------
static constexpr int TSZ = 128 * 128;
static constexpr int STG = 4 * TSZ;
static constexpr int SMEM_DYN = 2 * STG + 1024;

__global__ void __launch_bounds__(256, 1) gemm1_mma() {
    extern __shared__ char dsm[];
    uint32_t sb = (smem_u32(dsm) + 1023) & ~1023u;

    const int tid = threadIdx.x, lane = tid & 31, wid = tid >> 5;
    const int wm = wid >> 1, wn = wid & 1;
    const int n0 = blockIdx.x * 128;
    const int m0 = blockIdx.y * 128;

    auto load_chunk = [&](int kc, int buf) {
        int k0 = kc * 64;
        uint32_t base = sb + buf * STG;
#pragma unroll
        for (int it = 0; it < 16; it++) {
            int i = tid + it * 256;
            int arr = i >> 10;               // 0 Ah, 1 Al, 2 Bh, 3 Bl
            int r = (i >> 3) & 127, c = i & 7;
            const unsigned short* src;
            int row;
            if (arr < 2) { src = arr ? g_Fl : g_Fh; row = m0 + r; }
            else         { src = (arr == 3) ? g_w1l : g_w1h; row = n0 + r; }
            const void* g = src + (size_t)row * K1 + k0 + c * 8;
            cp_async16(base + arr * TSZ + swz(r * 128 + c * 16), g);
        }
    };

    const int g8 = lane >> 3, i8 = lane & 7;
    uint32_t patA[2], patB[4];
#pragma unroll
    for (int mt = 0; mt < 2; mt++) {
        int r = wm * 32 + mt * 16 + (g8 & 1) * 8 + i8;
        patA[mt] = swz((uint32_t)(r * 128 + (g8 >> 1) * 16));
    }
#pragma unroll
    for (int j = 0; j < 4; j++) {
        int r = wn * 64 + j * 16 + (g8 >> 1) * 8 + i8;
        patB[j] = swz((uint32_t)(r * 128 + (g8 & 1) * 16));
    }

    float acc[2][8][4];
#pragma unroll
    for (int a = 0; a < 2; a++)
#pragma unroll
        for (int b = 0; b < 8; b++)
#pragma unroll
            for (int c = 0; c < 4; c++) acc[a][b][c] = 0.0f;

    constexpr int NCH = K1 / 64;
    load_chunk(0, 0);
    CP_COMMIT();
    for (int c = 0; c < NCH; c++) {
        if (c + 1 < NCH) { load_chunk(c + 1, (c + 1) & 1); CP_COMMIT(); CP_WAIT(1); }
        else             { CP_WAIT(0); }
        __syncthreads();
        uint32_t base = sb + (c & 1) * STG;
#pragma unroll
        for (int ks = 0; ks < 4; ks++) {
            const uint32_t kx = (uint32_t)(ks * 32);
            uint32_t bh[4][4], bl[4][4];
#pragma unroll
            for (int j = 0; j < 4; j++) {
                ldm_x4(bh[j], base + 2 * TSZ + (patB[j] ^ kx));
                ldm_x4(bl[j], base + 3 * TSZ + (patB[j] ^ kx));
            }
#pragma unroll
            for (int mt = 0; mt < 2; mt++) {
                uint32_t ah[4], al[4];
                ldm_x4(ah, base + (patA[mt] ^ kx));
                ldm_x4(al, base + TSZ + (patA[mt] ^ kx));
#pragma unroll
                for (int nt = 0; nt < 8; nt++) {
                    const uint32_t* b_h = &bh[nt >> 1][(nt & 1) * 2];
                    const uint32_t* b_l = &bl[nt >> 1][(nt & 1) * 2];
                    mma_bf16(acc[mt][nt], ah, b_h);
                    mma_bf16(acc[mt][nt], ah, b_l);
                    mma_bf16(acc[mt][nt], al, b_h);
                }
            }
        }
        __syncthreads();
    }

    const int gr = lane >> 2, gc = (lane & 3) * 2;
#pragma unroll
    for (int mt = 0; mt < 2; mt++) {
#pragma unroll
        for (int nt = 0; nt < 8; nt++) {
            int n = n0 + wn * 64 + nt * 8 + gc;
#pragma unroll
            for (int h = 0; h < 2; h++) {
                int r = m0 + wm * 32 + mt * 16 + gr + h * 8;
                *reinterpret_cast<float2*>(g_P + (size_t)r * 512 + n) =
                    make_float2(acc[mt][nt][h * 2 + 0], acc[mt][nt][h * 2 + 1]);
            }
        }
    }
}

// ---------------------------------------------------------------------------
// GEMM2 with FUSED blend producer:
//   A[p,k] = relu( (w0*P[r0,k] + w1*P[r1,k] + w2*P[r2,k]) * s1[k] + t1[k] )
// built on the fly into split-bf16 smem tiles; B = W2 split (cp.async).
// out = relu(bn2(A @ W2^T)).
// ---------------------------------------------------------------------------
__global__ void __launch_bounds__(256, 1) gemm2_fused(float* __restrict__ Cout) {
    extern __shared__ char dsm[];
    uint32_t sbr = smem_u32(dsm);
    uint32_t sb  = (sbr + 1023) & ~1023u;
    char* smc = dsm + (sb - sbr);

    const int tid = threadIdx.x, lane = tid & 31, wid = tid >> 5;
    const int wm = wid >> 1, wn = wid & 1;
    const int n0 = blockIdx.x * 128;
    const int m0 = blockIdx.y * 128;

    // producer: thread pair (tid>>1) owns row r; (tid&1) picks 32-ch half of chunk
    const int pr = m0 + (tid >> 1);
    const int h32 = (tid & 1) * 32;
    const int bb = pr >> 13;
    const float* Pr0 = g_P + (size_t)(bb * Gc + g_idx[pr * 3 + 0]) * 512;
    const float* Pr1 = g_P + (size_t)(bb * Gc + g_idx[pr * 3 + 1]) * 512;
    const float* Pr2 = g_P + (size_t)(bb * Gc + g_idx[pr * 3 + 2]) * 512;
    const float w0 = g_wts[pr * 3 + 0], w1 = g_wts[pr * 3 + 1], w2 = g_wts[pr * 3 + 2];

    auto prodLoad = [&](int kc, int half, float4* rg) {
        int ch = kc * 64 + h32 + half * 16;
#pragma unroll
        for (int qq = 0; qq < 4; qq++) {
            rg[qq]     = *reinterpret_cast<const float4*>(Pr0 + ch + qq * 4);
            rg[4 + qq] = *reinterpret_cast<const float4*>(Pr1 + ch + qq * 4);
            rg[8 + qq] = *reinterpret_cast<const float4*>(Pr2 + ch + qq * 4);
        }
    };
    auto prodStore = [&](int kc, int half, const float4* rg, char* abase) {
        int ch = kc * 64 + h32 + half * 16;
        int r = tid >> 1;
#pragma unroll
        for (int u = 0; u < 2; u++) {
            union { unsigned short u16[8]; uint4 q; } Hp, Lp;
#pragma unroll
            for (int v = 0; v < 2; v++) {
                int qq = u * 2 + v;
                float4 a = rg[qq], c4 = rg[4 + qq], e = rg[8 + qq];
                float4 s = *reinterpret_cast<const float4*>(g_s1 + ch + qq * 4);
                float4 t = *reinterpret_cast<const float4*>(g_t1 + ch + qq * 4);
                float o0 = fmaxf(fmaf(w2 * e.x + w1 * c4.x + w0 * a.x, s.x, t.x), 0.0f);
                float o1 = fmaxf(fmaf(w2 * e.y + w1 * c4.y + w0 * a.y, s.y, t.y), 0.0f);
                float o2 = fmaxf(fmaf(w2 * e.z + w1 * c4.z + w0 * a.z, s.z, t.z), 0.0f);
                float o3 = fmaxf(fmaf(w2 * e.w + w1 * c4.w + w0 * a.w, s.w, t.w), 0.0f);
                Hp.u16[v*4+0] = bfhi(o0); Lp.u16[v*4+0] = bflo(o0, Hp.u16[v*4+0]);
                Hp.u16[v*4+1] = bfhi(o1); Lp.u16[v*4+1] = bflo(o1, Hp.u16[v*4+1]);
                Hp.u16[v*4+2] = bfhi(o2); Lp.u16[v*4+2] = bflo(o2, Hp.u16[v*4+2]);
                Hp.u16[v*4+3] = bfhi(o3); Lp.u16[v*4+3] = bflo(o3, Hp.u16[v*4+3]);
            }
            uint32_t off = swz((uint32_t)(r * 128 + h32 * 2 + half * 32 + u * 16));
            *reinterpret_cast<uint4*>(abase + off) = Hp.q;
            *reinterpret_cast<uint4*>(abase + TSZ + off) = Lp.q;
        }
    };
    auto loadB = [&](int kc, int buf) {
        int k0 = kc * 64;
        uint32_t base = sb + buf * STG;
#pragma unroll
        for (int it = 0; it < 8; it++) {
            int i = tid + it * 256;          // 0..2047
            int arr = 2 + (i >> 10);         // 2 Bh, 3 Bl
            int r = (i >> 3) & 127, c = i & 7;
            const unsigned short* src = (arr == 3) ? g_w2l : g_w2h;
            const void* g = src + (size_t)(n0 + r) * K2 + k0 + c * 8;
            cp_async16(base + arr * TSZ + swz(r * 128 + c * 16), g);
        }
    };

    const int g8 = lane >> 3, i8 = lane & 7;
    uint32_t patA[2], patB[4];
#pragma unroll
    for (int mt = 0; mt < 2; mt++) {
        int r = wm * 32 + mt * 16 + (g8 & 1) * 8 + i8;
        patA[mt] = swz((uint32_t)(r * 128 + (g8 >> 1) * 16));
    }
#pragma unroll
    for (int j = 0; j < 4; j++) {
        int r = wn * 64 + j * 16 + (g8 >> 1) * 8 + i8;
        patB[j] = swz((uint32_t)(r * 128 + (g8 & 1) * 16));
    }

    float acc[2][8][4];
#pragma unroll
    for (int a = 0; a < 2; a++)
#pragma unroll
        for (int b = 0; b < 8; b++)
#pragma unroll
            for (int c = 0; c < 4; c++) acc[a][b][c] = 0.0f;

    constexpr int NCH = K2 / 64;   // 8
    float4 rg[12];
    // prologue: chunk 0 (exposed once)
    loadB(0, 0); CP_COMMIT();
    prodLoad(0, 0, rg); prodStore(0, 0, rg, smc + 0 * STG);
    prodLoad(0, 1, rg); prodStore(0, 1, rg, smc + 0 * STG);

    for (int c = 0; c < NCH; c++) {
        char* nbc = smc + ((c + 1) & 1) * STG;
        if (c + 1 < NCH) {
            prodLoad(c + 1, 0, rg);            // LDG latency hidden by MMA below
            loadB(c + 1, (c + 1) & 1); CP_COMMIT(); CP_WAIT(1);
        } else CP_WAIT(0);
        __syncthreads();
        uint32_t base = sb + (c & 1) * STG;
#pragma unroll
        for (int ks = 0; ks < 4; ks++) {
            const uint32_t kx = (uint32_t)(ks * 32);
            uint32_t bh[4][4], bl[4][4];
#pragma unroll
            for (int j = 0; j < 4; j++) {
                ldm_x4(bh[j], base + 2 * TSZ + (patB[j] ^ kx));
                ldm_x4(bl[j], base + 3 * TSZ + (patB[j] ^ kx));
            }
#pragma unroll
            for (int mt = 0; mt < 2; mt++) {
                uint32_t ah[4], al[4];
                ldm_x4(ah, base + (patA[mt] ^ kx));
                ldm_x4(al, base + TSZ + (patA[mt] ^ kx));
#pragma unroll
                for (int nt = 0; nt < 8; nt++) {
                    const uint32_t* b_h = &bh[nt >> 1][(nt & 1) * 2];
                    const uint32_t* b_l = &bl[nt >> 1][(nt & 1) * 2];
                    mma_bf16(acc[mt][nt], ah, b_h);
                    mma_bf16(acc[mt][nt], ah, b_l);
                    mma_bf16(acc[mt][nt], al, b_h);
                }
            }
        }
        if (c + 1 < NCH) {
            prodStore(c + 1, 0, rg, nbc);
            prodLoad(c + 1, 1, rg);
            prodStore(c + 1, 1, rg, nbc);
        }
        __syncthreads();
    }

    const int gr = lane >> 2, gc = (lane & 3) * 2;
#pragma unroll
    for (int mt = 0; mt < 2; mt++) {
#pragma unroll
        for (int nt = 0; nt < 8; nt++) {
            int n = n0 + wn * 64 + nt * 8 + gc;
            float s0 = g_s2[n], s1v = g_s2[n + 1];
            float t0 = g_t2[n], t1v = g_t2[n + 1];
#pragma unroll
            for (int h = 0; h < 2; h++) {
                int r = m0 + wm * 32 + mt * 16 + gr + h * 8;
                float v0 = fmaxf(fmaf(acc[mt][nt][h * 2 + 0], s0, t0), 0.0f);
                float v1 = fmaxf(fmaf(acc[mt][nt][h * 2 + 1], s1v, t1v), 0.0f);
                *reinterpret_cast<float2*>(Cout + (size_t)r * 512 + n) = make_float2(v0, v1);
            }
        }
    }
}

// ---------------------------------------------------------------------------
extern "C" void kernel_launch(void* const* d_in, const int* in_sizes, int n_in,
                              void* d_out, int out_size) {
    (void)in_sizes; (void)n_in; (void)out_size;
    const float* xyz     = (const float*)d_in[0];
    const float* centers = (const float*)d_in[1];
    const float* H4      = (const float*)d_in[2];
    const float* H8      = (const float*)d_in[3];
    const float* H12     = (const float*)d_in[4];
    const float* w1      = (const float*)d_in[5];
    const float* b1      = (const float*)d_in[6];
    const float* g1      = (const float*)d_in[7];
    const float* be1     = (const float*)d_in[8];
    const float* m1      = (const float*)d_in[9];
    const float* v1      = (const float*)d_in[10];
    const float* w2      = (const float*)d_in[11];
    const float* b2      = (const float*)d_in[12];
    const float* g2      = (const float*)d_in[13];
    const float* be2     = (const float*)d_in[14];
    const float* m2      = (const float*)d_in[15];
    const float* v2      = (const float*)d_in[16];
    float* out = (float*)d_out;

    cudaFuncSetAttribute(gemm1_mma, cudaFuncAttributeMaxDynamicSharedMemorySize, SMEM_DYN);
    cudaFuncSetAttribute(gemm2_fused, cudaFuncAttributeMaxDynamicSharedMemorySize, SMEM_DYN);

    prep_kernel<<<1, 512>>>(b1, g1, be1, m1, v1, b2, g2, be2, m2, v2);
    convw_kernel<<<(512 * K1 + 255) / 256, 256>>>(w1, w2);
    convF_kernel<<<(Mg * 384 + 255) / 256, 256>>>(
        (const float4*)H4, (const float4*)H8, (const float4*)H12);
    knn_kernel<<<Mtot / 64, 256>>>(xyz, centers);

    gemm1_mma<<<dim3(4, Mg / 128), 256, SMEM_DYN>>>();
    gemm2_fused<<<dim3(4, Mtot / 128), 256, SMEM_DYN>>>(out);
}

// round 8
// speedup vs baseline: 1.9358x; 1.9358x over previous
#include <cuda_runtime.h>
#include <cuda_bf16.h>
#include <math.h>
#include <stdint.h>

#define Bc   4
#define Nc   8192
#define Gc   512
#define K1   1536
#define K2   512
#define Mtot (Bc * Nc)   // 32768
#define Mg   (Bc * Gc)   // 2048

// ---------------- scratch ----------------------------------------------------
__device__ unsigned short g_Fh[(size_t)Mg * K1];     // fused features hi (bf16)
__device__ unsigned short g_Fl[(size_t)Mg * K1];     // fused features lo
__device__ float          g_P [(size_t)Mg * 512];    // F @ W1^T (raw fp32)
__device__ unsigned short g_h1h[(size_t)Mtot * K2];  // hidden hi
__device__ unsigned short g_h1l[(size_t)Mtot * K2];  // hidden lo
__device__ unsigned short g_w1h[512 * K1], g_w1l[512 * K1];
__device__ unsigned short g_w2h[512 * K2], g_w2l[512 * K2];
__device__ int   g_idx[Mtot * 3];
__device__ float g_wts[Mtot * 3];
__device__ float g_s1[512], g_t1[512], g_s2[512], g_t2[512];

// ---------------- helpers ----------------------------------------------------
__device__ __forceinline__ uint32_t smem_u32(const void* p) {
    uint32_t a;
    asm("{ .reg .u64 t; cvta.to.shared.u64 t, %1; cvt.u32.u64 %0, t; }" : "=r"(a) : "l"(p));
    return a;
}
__device__ __forceinline__ void cp_async16(uint32_t dst, const void* src) {
    asm volatile("cp.async.cg.shared.global [%0], [%1], 16;" :: "r"(dst), "l"(src));
}
#define CP_COMMIT() asm volatile("cp.async.commit_group;" ::: "memory")
#define CP_WAIT(n)  asm volatile("cp.async.wait_group %0;" :: "n"(n) : "memory")

__device__ __forceinline__ void ldm_x4(uint32_t* r, uint32_t a) {
    asm volatile("ldmatrix.sync.aligned.m8n8.x4.shared.b16 {%0,%1,%2,%3}, [%4];"
                 : "=r"(r[0]), "=r"(r[1]), "=r"(r[2]), "=r"(r[3]) : "r"(a));
}
__device__ __forceinline__ void mma_bf16(float* c, const uint32_t* a, const uint32_t* b) {
    asm volatile("mma.sync.aligned.m16n8k16.row.col.f32.bf16.bf16.f32 "
                 "{%0,%1,%2,%3}, {%4,%5,%6,%7}, {%8,%9}, {%0,%1,%2,%3};"
                 : "+f"(c[0]), "+f"(c[1]), "+f"(c[2]), "+f"(c[3])
                 : "r"(a[0]), "r"(a[1]), "r"(a[2]), "r"(a[3]), "r"(b[0]), "r"(b[1]));
}
__device__ __forceinline__ uint32_t swz(uint32_t o) { return o ^ ((o >> 3) & 0x70); }
__device__ __forceinline__ unsigned short bfhi(float v) {
    __nv_bfloat16 h = __float2bfloat16(v);
    return *(unsigned short*)&h;
}
__device__ __forceinline__ unsigned short bflo(float v, unsigned short hb) {
    __nv_bfloat16 h; *(unsigned short*)&h = hb;
    __nv_bfloat16 l = __float2bfloat16(v - __bfloat162float(h));
    return *(unsigned short*)&l;
}

// ---------------------------------------------------------------------------
__global__ void prep_kernel(const float* __restrict__ b1, const float* __restrict__ g1,
                            const float* __restrict__ be1, const float* __restrict__ m1,
                            const float* __restrict__ v1,
                            const float* __restrict__ b2, const float* __restrict__ g2,
                            const float* __restrict__ be2, const float* __restrict__ m2,
                            const float* __restrict__ v2) {
    int i = threadIdx.x;
    if (i < 512) {
        float s = g1[i] * rsqrtf(v1[i] + 1e-5f);
        g_s1[i] = s;
        g_t1[i] = (b1[i] - m1[i]) * s + be1[i];
        float s2 = g2[i] * rsqrtf(v2[i] + 1e-5f);
        g_s2[i] = s2;
        g_t2[i] = (b2[i] - m2[i]) * s2 + be2[i];
    }
}

__global__ void convw_kernel(const float* __restrict__ w1, const float* __restrict__ w2) {
    int i = blockIdx.x * 256 + threadIdx.x;
    if (i < 512 * K1) {
        float v = w1[i];
        unsigned short h = bfhi(v);
        g_w1h[i] = h;
        g_w1l[i] = bflo(v, h);
    }
    if (i < 512 * K2) {
        float v = w2[i];
        unsigned short h = bfhi(v);
        g_w2h[i] = h;
        g_w2l[i] = bflo(v, h);
    }
}

// fused features F -> bf16 hi/lo
__global__ void convF_kernel(const float4* __restrict__ H4,
                             const float4* __restrict__ H8,
                             const float4* __restrict__ H12) {
    int gid = blockIdx.x * 256 + threadIdx.x;   // < Mg * 384
    if (gid >= Mg * 384) return;
    int row = gid / 384;
    int c4  = gid - row * 384;
    int seg = c4 >> 7;
    int off = c4 & 127;
    const float4* H = (seg == 0) ? H4 : ((seg == 1) ? H8 : H12);
    float4 v = H[(size_t)row * 128 + off];
    float o[4] = {v.x, v.y, v.z, v.w};
    union { unsigned short u[4]; uint2 q; } Hq, Lq;
#pragma unroll
    for (int j = 0; j < 4; j++) {
        Hq.u[j] = bfhi(o[j]);
        Lq.u[j] = bflo(o[j], Hq.u[j]);
    }
    *reinterpret_cast<uint2*>(g_Fh + (size_t)gid * 4) = Hq.q;
    *reinterpret_cast<uint2*>(g_Fl + (size_t)gid * 4) = Lq.q;
}

// ---------------------------------------------------------------------------
// 3-NN: bit-exact serial version (validated R2/R6 — fastest measured variant)
// ---------------------------------------------------------------------------
__global__ void knn_kernel(const float* __restrict__ xyz,
                           const float* __restrict__ centers) {
    __shared__ float4 sc[Gc];
    int p = blockIdx.x * blockDim.x + threadIdx.x;
    int b = p >> 13;
    for (int g = threadIdx.x; g < Gc; g += blockDim.x) {
        float cx = centers[(b * Gc + g) * 3 + 0];
        float cy = centers[(b * Gc + g) * 3 + 1];
        float cz = centers[(b * Gc + g) * 3 + 2];
        float cc = __fadd_rn(__fadd_rn(__fmul_rn(cx, cx), __fmul_rn(cy, cy)),
                             __fmul_rn(cz, cz));
        sc[g] = make_float4(cx, cy, cz, cc);
    }
    __syncthreads();

    float x = xyz[p * 3 + 0], y = xyz[p * 3 + 1], z = xyz[p * 3 + 2];
    float xx = __fadd_rn(__fadd_rn(__fmul_rn(x, x), __fmul_rn(y, y)),
                         __fmul_rn(z, z));
    float d0 = INFINITY, d1 = INFINITY, d2 = INFINITY;
    int   i0 = 0, i1 = 0, i2 = 0;
    for (int g = 0; g < Gc; g++) {
        float4 c = sc[g];
        float dot = __fmaf_rn(z, c.z, __fmaf_rn(y, c.y, __fmul_rn(x, c.x)));
        float d   = __fsub_rn(__fadd_rn(xx, c.w), __fmul_rn(2.0f, dot));
        if (d < d0)      { d2 = d1; i2 = i1; d1 = d0; i1 = i0; d0 = d; i0 = g; }
        else if (d < d1) { d2 = d1; i2 = i1; d1 = d;  i1 = g; }
        else if (d < d2) { d2 = d;  i2 = g; }
    }
    float r0 = __fdiv_rn(1.0f, __fadd_rn(d0, 1e-8f));
    float r1 = __fdiv_rn(1.0f, __fadd_rn(d1, 1e-8f));
    float r2 = __fdiv_rn(1.0f, __fadd_rn(d2, 1e-8f));
    float rs = __fadd_rn(__fadd_rn(r0, r1), r2);
    g_idx[p * 3 + 0] = i0; g_idx[p * 3 + 1] = i1; g_idx[p * 3 + 2] = i2;
    g_wts[p * 3 + 0] = __fdiv_rn(r0, rs);
    g_wts[p * 3 + 1] = __fdiv_rn(r1, rs);
    g_wts[p * 3 + 2] = __fdiv_rn(r2, rs);
}

// ---------------------------------------------------------------------------
// Blend (validated R6): h1 = relu(bn1(blend(P))), split bf16 out
// ---------------------------------------------------------------------------
__global__ void blend_kernel() {
    int p = blockIdx.x * 2 + (threadIdx.x >> 7);
    int j = threadIdx.x & 127;
    int b = p >> 13;
    int r0 = b * Gc + g_idx[p * 3 + 0];
    int r1 = b * Gc + g_idx[p * 3 + 1];
    int r2 = b * Gc + g_idx[p * 3 + 2];
    float w0 = g_wts[p * 3 + 0], w1 = g_wts[p * 3 + 1], w2 = g_wts[p * 3 + 2];
    const float4* P4 = reinterpret_cast<const float4*>(g_P);
    float4 a = P4[(size_t)r0 * 128 + j];
    float4 c = P4[(size_t)r1 * 128 + j];
    float4 e = P4[(size_t)r2 * 128 + j];
    float4 s = reinterpret_cast<const float4*>(g_s1)[j];
    float4 t = reinterpret_cast<const float4*>(g_t1)[j];
    float o[4];
    o[0] = fmaxf(fmaf(w2*e.x + w1*c.x + w0*a.x, s.x, t.x), 0.0f);
    o[1] = fmaxf(fmaf(w2*e.y + w1*c.y + w0*a.y, s.y, t.y), 0.0f);
    o[2] = fmaxf(fmaf(w2*e.z + w1*c.z + w0*a.z, s.z, t.z), 0.0f);
    o[3] = fmaxf(fmaf(w2*e.w + w1*c.w + w0*a.w, s.w, t.w), 0.0f);
    union { unsigned short u[4]; uint2 q; } Hq, Lq;
#pragma unroll
    for (int k = 0; k < 4; k++) {
        Hq.u[k] = bfhi(o[k]);
        Lq.u[k] = bflo(o[k], Hq.u[k]);
    }
    *reinterpret_cast<uint2*>(g_h1h + (size_t)p * 512 + j * 4) = Hq.q;
    *reinterpret_cast<uint2*>(g_h1l + (size_t)p * 512 + j * 4) = Lq.q;
}

// ---------------------------------------------------------------------------
// mma.sync bf16 3-term split GEMM, templated m-tile (MT: BM = MT*64).
// MT=1 -> 48 KB/stage -> 2 CTAs/SM; more CTAs for wave parallelism.
// LAYER==1: A = g_Fh/g_Fl (M=2048), raw fp32 -> g_P
// LAYER==2: A = g_h1h/g_h1l (M=32768), BN2+ReLU -> Cout
// ---------------------------------------------------------------------------
template <int MT> struct TileCfg {
    static constexpr int BM   = MT * 64;
    static constexpr int ATSZ = BM * 128;        // one A array tile bytes
    static constexpr int BTSZ = 128 * 128;       // one B array tile bytes
    static constexpr int STAGE = 2 * ATSZ + 2 * BTSZ;
    static constexpr int SMEM  = 2 * STAGE + 1024;
};

template <int K, int LAYER, int MT>
__global__ void __launch_bounds__(256, 2) gemm_mma(float* __restrict__ Cout) {
    constexpr int BM   = TileCfg<MT>::BM;
    constexpr int ATSZ = TileCfg<MT>::ATSZ;
    constexpr int BTSZ = TileCfg<MT>::BTSZ;
    constexpr int STAGE = TileCfg<MT>::STAGE;

    extern __shared__ char dsm[];
    uint32_t sb = (smem_u32(dsm) + 1023) & ~1023u;

    const int tid = threadIdx.x, lane = tid & 31, wid = tid >> 5;
    const int wm = wid >> 1, wn = wid & 1;
    const int n0 = blockIdx.x * 128;
    const int m0 = blockIdx.y * BM;

    const unsigned short* Ah = (LAYER == 1) ? g_Fh  : g_h1h;
    const unsigned short* Al = (LAYER == 1) ? g_Fl  : g_h1l;
    const unsigned short* Wh = (LAYER == 1) ? g_w1h : g_w2h;
    const unsigned short* Wl = (LAYER == 1) ? g_w1l : g_w2l;

    auto load_chunk = [&](int kc, int buf) {
        int k0 = kc * 64;
        uint32_t base = sb + buf * STAGE;
#pragma unroll
        for (int i = tid; i < BM * 8; i += 256) {     // A hi+lo
            int r = i >> 3, c = i & 7;
            size_t go = (size_t)(m0 + r) * K + k0 + c * 8;
            uint32_t off = swz((uint32_t)(r * 128 + c * 16));
            cp_async16(base + off, Ah + go);
            cp_async16(base + ATSZ + off, Al + go);
        }
#pragma unroll
        for (int i = tid; i < 128 * 8; i += 256) {    // B hi+lo
            int r = i >> 3, c = i & 7;
            size_t go = (size_t)(n0 + r) * K + k0 + c * 8;
            uint32_t off = swz((uint32_t)(r * 128 + c * 16));
            cp_async16(base + 2 * ATSZ + off, Wh + go);
            cp_async16(base + 2 * ATSZ + BTSZ + off, Wl + go);
        }
    };

    const int g8 = lane >> 3, i8 = lane & 7;
    uint32_t patA[MT], patB[4];
#pragma unroll
    for (int mt = 0; mt < MT; mt++) {
        int r = wm * (16 * MT) + mt * 16 + (g8 & 1) * 8 + i8;
        patA[mt] = swz((uint32_t)(r * 128 + (g8 >> 1) * 16));
    }
#pragma unroll
    for (int j = 0; j < 4; j++) {
        int r = wn * 64 + j * 16 + (g8 >> 1) * 8 + i8;
        patB[j] = swz((uint32_t)(r * 128 + (g8 & 1) * 16));
    }

    float acc[MT][8][4];
#pragma unroll
    for (int a = 0; a < MT; a++)
#pragma unroll
        for (int b = 0; b < 8; b++)
#pragma unroll
            for (int c = 0; c < 4; c++) acc[a][b][c] = 0.0f;

    constexpr int NCH = K / 64;
    load_chunk(0, 0);
    CP_COMMIT();
    for (int c = 0; c < NCH; c++) {
        if (c + 1 < NCH) { load_chunk(c + 1, (c + 1) & 1); CP_COMMIT(); CP_WAIT(1); }
        else             { CP_WAIT(0); }
        __syncthreads();
        uint32_t base = sb + (c & 1) * STAGE;
#pragma unroll
        for (int ks = 0; ks < 4; ks++) {
            const uint32_t kx = (uint32_t)(ks * 32);
            uint32_t bh[4][4], bl[4][4];
#pragma unroll
            for (int j = 0; j < 4; j++) {
                ldm_x4(bh[j], base + 2 * ATSZ + (patB[j] ^ kx));
                ldm_x4(bl[j], base + 2 * ATSZ + BTSZ + (patB[j] ^ kx));
            }
#pragma unroll
            for (int mt = 0; mt < MT; mt++) {
                uint32_t ah[4], al[4];
                ldm_x4(ah, base + (patA[mt] ^ kx));
                ldm_x4(al, base + ATSZ + (patA[mt] ^ kx));
#pragma unroll
                for (int nt = 0; nt < 8; nt++) {
                    const uint32_t* b_h = &bh[nt >> 1][(nt & 1) * 2];
                    const uint32_t* b_l = &bl[nt >> 1][(nt & 1) * 2];
                    mma_bf16(acc[mt][nt], ah, b_h);
                    mma_bf16(acc[mt][nt], ah, b_l);
                    mma_bf16(acc[mt][nt], al, b_h);
                }
            }
        }
        __syncthreads();
    }

    const int gr = lane >> 2, gc = (lane & 3) * 2;
#pragma unroll
    for (int mt = 0; mt < MT; mt++) {
#pragma unroll
        for (int nt = 0; nt < 8; nt++) {
            int n = n0 + wn * 64 + nt * 8 + gc;
#pragma unroll
            for (int h = 0; h < 2; h++) {
                int r = m0 + wm * (16 * MT) + mt * 16 + gr + h * 8;
                if (LAYER == 1) {
                    *reinterpret_cast<float2*>(g_P + (size_t)r * 512 + n) =
                        make_float2(acc[mt][nt][h * 2 + 0], acc[mt][nt][h * 2 + 1]);
                } else {
                    float s0 = g_s2[n], s1v = g_s2[n + 1];
                    float t0 = g_t2[n], t1v = g_t2[n + 1];
                    float v0 = fmaxf(fmaf(acc[mt][nt][h * 2 + 0], s0, t0), 0.0f);
                    float v1 = fmaxf(fmaf(acc[mt][nt][h * 2 + 1], s1v, t1v), 0.0f);
                    *reinterpret_cast<float2*>(Cout + (size_t)r * 512 + n) = make_float2(v0, v1);
                }
            }
        }
    }
}

// ---------------------------------------------------------------------------
extern "C" void kernel_launch(void* const* d_in, const int* in_sizes, int n_in,
                              void* d_out, int out_size) {
    (void)in_sizes; (void)n_in; (void)out_size;
    const float* xyz     = (const float*)d_in[0];
    const float* centers = (const float*)d_in[1];
    const float* H4      = (const float*)d_in[2];
    const float* H8      = (const float*)d_in[3];
    const float* H12     = (const float*)d_in[4];
    const float* w1      = (const float*)d_in[5];
    const float* b1      = (const float*)d_in[6];
    const float* g1      = (const float*)d_in[7];
    const float* be1     = (const float*)d_in[8];
    const float* m1      = (const float*)d_in[9];
    const float* v1      = (const float*)d_in[10];
    const float* w2      = (const float*)d_in[11];
    const float* b2      = (const float*)d_in[12];
    const float* g2      = (const float*)d_in[13];
    const float* be2     = (const float*)d_in[14];
    const float* m2      = (const float*)d_in[15];
    const float* v2      = (const float*)d_in[16];
    float* out = (float*)d_out;

    constexpr int SM1 = TileCfg<1>::SMEM;   // 99 KB -> 2 CTAs/SM
    cudaFuncSetAttribute(gemm_mma<K1, 1, 1>, cudaFuncAttributeMaxDynamicSharedMemorySize, SM1);
    cudaFuncSetAttribute(gemm_mma<K2, 2, 1>, cudaFuncAttributeMaxDynamicSharedMemorySize, SM1);

    prep_kernel<<<1, 512>>>(b1, g1, be1, m1, v1, b2, g2, be2, m2, v2);
    convw_kernel<<<(512 * K1 + 255) / 256, 256>>>(w1, w2);
    convF_kernel<<<(Mg * 384 + 255) / 256, 256>>>(
        (const float4*)H4, (const float4*)H8, (const float4*)H12);
    knn_kernel<<<Mtot / 256, 256>>>(xyz, centers);

    // P[2048,512] = F @ W1^T   (128 CTAs)
    gemm_mma<K1, 1, 1><<<dim3(4, Mg / 64), 256, SM1>>>(nullptr);
    // blend + BN1 + ReLU -> h1 (hi/lo bf16)
    blend_kernel<<<Mtot / 2, 256>>>();
    // out = relu(bn2(h1 @ W2^T))   (2048 CTAs, 2/SM)
    gemm_mma<K2, 2, 1><<<dim3(4, Mtot / 64), 256, SM1>>>(out);
}